// round 14
// baseline (speedup 1.0000x reference)
#include <cuda_runtime.h>

// Problem constants
#define BB   4
#define LL   2048
#define DD   1024
#define HH   16
#define DKV  64
#define NEGV (-1e10f)

#define BL    (BB*LL)                // 8192 rows
#define HEADS (BB*HH)                // 64
#define NROWS (HEADS*LL)             // 131072 attention rows
#define NTILE 16                     // 2048/128 col tiles in energy
static const long long OUT_ELEMS  = (long long)BB*LL*DD;          // 8,388,608
static const long long ATTN_ELEMS = (long long)BB*HH*LL*LL;       // 268,435,456

// ---------------- device scratch (no allocations allowed) ----------------
__device__ __align__(16) float g_qh [BB*HH*LL*DKV];   // [b,h,l,d] 32MB
__device__ __align__(16) float g_kh [BB*HH*LL*DKV];
__device__ __align__(16) float g_vh [BB*HH*LL*DKV];
__device__ __align__(16) float g_ctx[BB*LL*DD];       // [b,l,h*d] 32MB
__device__ __align__(16) float g_z  [BB*LL*DD];       // pre-LN    32MB
__device__ __align__(16) float g_attn_fb[268435456];  // fallback if attn not in d_out

// split-softmax stats: [tile][global_row] layout for coalesced reduce reads
__device__ __align__(16) float g_stat_m[NTILE * NROWS];   // per-tile row max
__device__ __align__(16) float g_stat_s[NTILE * NROWS];   // per-tile sum exp(s - m_tile)
__device__ __align__(16) float g_rowM  [NROWS];           // global row max
__device__ __align__(16) float g_rowIS [NROWS];           // 1 / global row sum

// =====================================================================
// Kernel 1: fused QKV projections.  X[8192,1024] @ W[1024,1024] + b,
// stored directly in head layout [b,h,l,d].  z = 0/1/2 selects q/k/v.
// 128x128x8 tile, 256 threads, 8x8 per thread.
// =====================================================================
__global__ __launch_bounds__(256) void qkv_proj_kernel(
    const float* __restrict__ q, const float* __restrict__ k, const float* __restrict__ v,
    const float* __restrict__ Wq, const float* __restrict__ Wk, const float* __restrict__ Wv,
    const float* __restrict__ bq, const float* __restrict__ bk, const float* __restrict__ bv)
{
    const int zz = blockIdx.z;
    const float* __restrict__ A    = (zz == 0) ? q  : (zz == 1) ? k  : v;
    const float* __restrict__ W    = (zz == 0) ? Wq : (zz == 1) ? Wk : Wv;
    const float* __restrict__ bias = (zz == 0) ? bq : (zz == 1) ? bk : bv;
    float* __restrict__ C          = (zz == 0) ? g_qh : (zz == 1) ? g_kh : g_vh;

    __shared__ float As[8][132];   // A tile transposed [k][m], padded
    __shared__ float Bs[8][128];   // B tile natural    [k][n]

    const int tid  = threadIdx.x;
    const int tx   = tid & 15;
    const int ty   = tid >> 4;
    const int row0 = blockIdx.y * 128;
    const int col0 = blockIdx.x * 128;

    const int arow = tid >> 1;          // 0..127
    const int acol = (tid & 1) * 4;     // 0 or 4
    const int brow = tid >> 5;          // 0..7
    const int bcol = (tid & 31) * 4;    // 0..124

    float acc[8][8] = {};

    for (int kt = 0; kt < DD; kt += 8) {
        float4 a4 = *(const float4*)(A + (size_t)(row0 + arow) * DD + kt + acol);
        As[acol + 0][arow] = a4.x; As[acol + 1][arow] = a4.y;
        As[acol + 2][arow] = a4.z; As[acol + 3][arow] = a4.w;
        float4 b4 = *(const float4*)(W + (size_t)(kt + brow) * (HH * DKV) + col0 + bcol);
        *(float4*)&Bs[brow][bcol] = b4;
        __syncthreads();
        #pragma unroll
        for (int kk = 0; kk < 8; kk++) {
            float ar[8], br[8];
            #pragma unroll
            for (int i = 0; i < 8; i++) ar[i] = As[kk][ty * 8 + i];
            #pragma unroll
            for (int j = 0; j < 8; j++) br[j] = Bs[kk][tx * 8 + j];
            #pragma unroll
            for (int i = 0; i < 8; i++)
                #pragma unroll
                for (int j = 0; j < 8; j++)
                    acc[i][j] = fmaf(ar[i], br[j], acc[i][j]);
        }
        __syncthreads();
    }

    const int n0 = col0 + tx * 8;         // stays within one head (64 % 8 == 0)
    const int h  = n0 >> 6;
    const int d0 = n0 & 63;
    const float4 bs0 = *(const float4*)(bias + n0);
    const float4 bs1 = *(const float4*)(bias + n0 + 4);
    #pragma unroll
    for (int i = 0; i < 8; i++) {
        const int m  = row0 + ty * 8 + i;
        const int bb = m >> 11;           // / 2048
        const int l  = m & 2047;
        float* dst = C + (((size_t)(bb * HH + h)) * LL + l) * DKV + d0;
        float4 o0 = make_float4(acc[i][0] + bs0.x, acc[i][1] + bs0.y,
                                acc[i][2] + bs0.z, acc[i][3] + bs0.w);
        float4 o1 = make_float4(acc[i][4] + bs1.x, acc[i][5] + bs1.y,
                                acc[i][6] + bs1.z, acc[i][7] + bs1.w);
        *(float4*)dst       = o0;
        *(float4*)(dst + 4) = o1;
    }
}

// =====================================================================
// Kernel 2: energy = Q Kᵀ / 8, masked.  Per (b,h): [2048,64]x[64,2048].
// 128x128 tile.  Writes masked energy to attn buffer AND per-(row,tile)
// softmax partials (max, sumexp) via half-warp shfl reductions.
// =====================================================================
__global__ __launch_bounds__(256) void energy_kernel(
    const int* __restrict__ mask, float* __restrict__ attn_arg)
{
    float* __restrict__ attn = attn_arg ? attn_arg : g_attn_fb;
    const int z = blockIdx.z;
    const int b = z >> 4;
    const float* __restrict__ Q  = g_qh + (size_t)z * (LL * DKV);
    const float* __restrict__ Kh = g_kh + (size_t)z * (LL * DKV);
    float* __restrict__ S = attn + (size_t)z * LL * LL;

    __shared__ float As[8][132];
    __shared__ float Bs[8][132];

    const int tid  = threadIdx.x;
    const int tx   = tid & 15;
    const int ty   = tid >> 4;
    const int row0 = blockIdx.y * 128;
    const int col0 = blockIdx.x * 128;

    const int arow = tid >> 1;
    const int acol = (tid & 1) * 4;

    float acc[8][8] = {};

    #pragma unroll
    for (int kt = 0; kt < DKV; kt += 8) {
        float4 a4 = *(const float4*)(Q  + (size_t)(row0 + arow) * DKV + kt + acol);
        float4 b4 = *(const float4*)(Kh + (size_t)(col0 + arow) * DKV + kt + acol);
        As[acol + 0][arow] = a4.x; As[acol + 1][arow] = a4.y;
        As[acol + 2][arow] = a4.z; As[acol + 3][arow] = a4.w;
        Bs[acol + 0][arow] = b4.x; Bs[acol + 1][arow] = b4.y;
        Bs[acol + 2][arow] = b4.z; Bs[acol + 3][arow] = b4.w;
        __syncthreads();
        #pragma unroll
        for (int kk = 0; kk < 8; kk++) {
            float ar[8], br[8];
            #pragma unroll
            for (int i = 0; i < 8; i++) ar[i] = As[kk][ty * 8 + i];
            #pragma unroll
            for (int j = 0; j < 8; j++) br[j] = Bs[kk][tx * 8 + j];
            #pragma unroll
            for (int i = 0; i < 8; i++)
                #pragma unroll
                for (int j = 0; j < 8; j++)
                    acc[i][j] = fmaf(ar[i], br[j], acc[i][j]);
        }
        __syncthreads();
    }

    const int n0 = col0 + tx * 8;
    #pragma unroll
    for (int i = 0; i < 8; i++) {
        const int m = row0 + ty * 8 + i;
        const int* mrow = mask + ((size_t)b * LL + m) * LL + n0;
        const int4 m0 = *(const int4*)(mrow);
        const int4 m1 = *(const int4*)(mrow + 4);
        float vals[8];
        vals[0] = m0.x ? acc[i][0] * 0.125f : NEGV;
        vals[1] = m0.y ? acc[i][1] * 0.125f : NEGV;
        vals[2] = m0.z ? acc[i][2] * 0.125f : NEGV;
        vals[3] = m0.w ? acc[i][3] * 0.125f : NEGV;
        vals[4] = m1.x ? acc[i][4] * 0.125f : NEGV;
        vals[5] = m1.y ? acc[i][5] * 0.125f : NEGV;
        vals[6] = m1.z ? acc[i][6] * 0.125f : NEGV;
        vals[7] = m1.w ? acc[i][7] * 0.125f : NEGV;
        float* srow = S + (size_t)m * LL + n0;
        *(float4*)srow       = make_float4(vals[0], vals[1], vals[2], vals[3]);
        *(float4*)(srow + 4) = make_float4(vals[4], vals[5], vals[6], vals[7]);

        // per-(row, 128-col-tile) softmax partials across the 16 tx lanes
        float mx = vals[0];
        #pragma unroll
        for (int j = 1; j < 8; j++) mx = fmaxf(mx, vals[j]);
        #pragma unroll
        for (int off = 8; off > 0; off >>= 1)
            mx = fmaxf(mx, __shfl_xor_sync(0xffffffffu, mx, off));
        float se = 0.0f;
        #pragma unroll
        for (int j = 0; j < 8; j++) se += __expf(vals[j] - mx);
        #pragma unroll
        for (int off = 8; off > 0; off >>= 1)
            se += __shfl_xor_sync(0xffffffffu, se, off);
        if (tx == 0) {
            const size_t sidx = (size_t)blockIdx.x * NROWS + (size_t)z * LL + m;
            g_stat_m[sidx] = mx;
            g_stat_s[sidx] = se;
        }
    }
}

// =====================================================================
// Kernel 2b: fold 16 per-tile partials into per-row (max, 1/sum).
// =====================================================================
__global__ __launch_bounds__(256) void stat_reduce_kernel()
{
    const int row = blockIdx.x * 256 + threadIdx.x;   // 0..131071
    float m[NTILE];
    float M = -3.4e38f;
    #pragma unroll
    for (int t = 0; t < NTILE; t++) {
        m[t] = g_stat_m[(size_t)t * NROWS + row];
        M = fmaxf(M, m[t]);
    }
    float S = 0.0f;
    #pragma unroll
    for (int t = 0; t < NTILE; t++)
        S += g_stat_s[(size_t)t * NROWS + row] * __expf(m[t] - M);
    g_rowM [row] = M;
    g_rowIS[row] = 1.0f / S;
}

// =====================================================================
// Kernel 3: ctx = softmax(energy) @ V per (b,h): [2048,2048]x[2048,64].
// 256x64 tile, BK=16, 256 threads, 8x8 per thread.  Normalizes the raw
// energies on load (p = exp(s-M)/S), writes normalized attn back to the
// output buffer (each element visited exactly once), writes ctx
// [b,l,h*64+d].
// =====================================================================
__global__ __launch_bounds__(256, 2) void pv_kernel(float* __restrict__ attn_arg)
{
    float* __restrict__ attn = attn_arg ? attn_arg : g_attn_fb;
    const int z = blockIdx.z;
    const int b = z >> 4;
    const int h = z & 15;
    float* __restrict__ A        = attn + (size_t)z * LL * LL;
    const float* __restrict__ Vv = g_vh + (size_t)z * (LL * DKV);

    __shared__ float As[16][258];   // [k][m], pitch 258 -> conflict-free stores
    __shared__ float Bs[16][64];    // [k][n]

    const int tid  = threadIdx.x;
    const int tx   = tid & 7;     // 8 col groups
    const int ty   = tid >> 3;    // 32 row groups
    const int row0 = blockIdx.y * 256;

    // A loader: 4 rows per thread (lr, lr+64, lr+128, lr+192), one float4 each
    const int lr = tid >> 2;            // 0..63
    const int lc = (tid & 3) * 4;       // 0,4,8,12
    // V loader
    const int brow = tid >> 4;          // 0..15
    const int bcol = (tid & 15) * 4;    // 0..60

    float Mr[4], iS[4];
    #pragma unroll
    for (int qq = 0; qq < 4; qq++) {
        const int grow = z * LL + row0 + lr + 64 * qq;
        Mr[qq] = g_rowM [grow];
        iS[qq] = g_rowIS[grow];
    }

    float acc[8][8] = {};

    for (int kt = 0; kt < LL; kt += 16) {
        #pragma unroll
        for (int qq = 0; qq < 4; qq++) {
            const int r = lr + 64 * qq;
            float* gp = A + (size_t)(row0 + r) * LL + kt + lc;
            float4 s4 = *(const float4*)gp;
            float4 p4;
            p4.x = __expf(s4.x - Mr[qq]) * iS[qq];
            p4.y = __expf(s4.y - Mr[qq]) * iS[qq];
            p4.z = __expf(s4.z - Mr[qq]) * iS[qq];
            p4.w = __expf(s4.w - Mr[qq]) * iS[qq];
            *(float4*)gp = p4;                    // normalized attn output
            As[lc + 0][r] = p4.x; As[lc + 1][r] = p4.y;
            As[lc + 2][r] = p4.z; As[lc + 3][r] = p4.w;
        }
        float4 b4 = *(const float4*)(Vv + (size_t)(kt + brow) * DKV + bcol);
        *(float4*)&Bs[brow][bcol] = b4;
        __syncthreads();
        #pragma unroll
        for (int kk = 0; kk < 16; kk++) {
            float ar[8], br[8];
            #pragma unroll
            for (int i = 0; i < 8; i++) ar[i] = As[kk][ty * 8 + i];
            #pragma unroll
            for (int j = 0; j < 8; j++) br[j] = Bs[kk][tx * 8 + j];
            #pragma unroll
            for (int i = 0; i < 8; i++)
                #pragma unroll
                for (int j = 0; j < 8; j++)
                    acc[i][j] = fmaf(ar[i], br[j], acc[i][j]);
        }
        __syncthreads();
    }

    #pragma unroll
    for (int i = 0; i < 8; i++) {
        const int m = row0 + ty * 8 + i;
        float* dst = g_ctx + ((size_t)(b * LL + m)) * DD + h * DKV + tx * 8;
        *(float4*)dst       = make_float4(acc[i][0], acc[i][1], acc[i][2], acc[i][3]);
        *(float4*)(dst + 4) = make_float4(acc[i][4], acc[i][5], acc[i][6], acc[i][7]);
    }
}

// ---------------- block reduction (256 threads) ----------------
__device__ __forceinline__ float blockReduceSum256(float v, float* red) {
    #pragma unroll
    for (int o = 16; o > 0; o >>= 1) v += __shfl_xor_sync(0xffffffffu, v, o);
    const int w = threadIdx.x >> 5;
    if ((threadIdx.x & 31) == 0) red[w] = v;
    __syncthreads();
    if (threadIdx.x < 32) {
        float r = (threadIdx.x < 8) ? red[threadIdx.x] : 0.0f;
        #pragma unroll
        for (int o = 4; o > 0; o >>= 1) r += __shfl_xor_sync(0xffffffffu, r, o);
        if (threadIdx.x == 0) red[0] = r;
    }
    __syncthreads();
    const float r = red[0];
    __syncthreads();
    return r;
}

// =====================================================================
// Kernel 4: z = ctx @ Wo + bo.  Standard 128x128x8 SGEMM.
// =====================================================================
__global__ __launch_bounds__(256) void outproj_kernel(
    const float* __restrict__ Wo, const float* __restrict__ bo)
{
    __shared__ float As[8][132];
    __shared__ float Bs[8][128];

    const int tid  = threadIdx.x;
    const int tx   = tid & 15;
    const int ty   = tid >> 4;
    const int row0 = blockIdx.y * 128;
    const int col0 = blockIdx.x * 128;

    const int arow = tid >> 1;
    const int acol = (tid & 1) * 4;
    const int brow = tid >> 5;
    const int bcol = (tid & 31) * 4;

    float acc[8][8] = {};

    for (int kt = 0; kt < DD; kt += 8) {
        float4 a4 = *(const float4*)(g_ctx + (size_t)(row0 + arow) * DD + kt + acol);
        As[acol + 0][arow] = a4.x; As[acol + 1][arow] = a4.y;
        As[acol + 2][arow] = a4.z; As[acol + 3][arow] = a4.w;
        float4 b4 = *(const float4*)(Wo + (size_t)(kt + brow) * DD + col0 + bcol);
        *(float4*)&Bs[brow][bcol] = b4;
        __syncthreads();
        #pragma unroll
        for (int kk = 0; kk < 8; kk++) {
            float ar[8], br[8];
            #pragma unroll
            for (int i = 0; i < 8; i++) ar[i] = As[kk][ty * 8 + i];
            #pragma unroll
            for (int j = 0; j < 8; j++) br[j] = Bs[kk][tx * 8 + j];
            #pragma unroll
            for (int i = 0; i < 8; i++)
                #pragma unroll
                for (int j = 0; j < 8; j++)
                    acc[i][j] = fmaf(ar[i], br[j], acc[i][j]);
        }
        __syncthreads();
    }

    const int n0 = col0 + tx * 8;
    const float4 bs0 = *(const float4*)(bo + n0);
    const float4 bs1 = *(const float4*)(bo + n0 + 4);
    #pragma unroll
    for (int i = 0; i < 8; i++) {
        const int m = row0 + ty * 8 + i;
        float* dst = g_z + (size_t)m * DD + n0;
        *(float4*)dst       = make_float4(acc[i][0] + bs0.x, acc[i][1] + bs0.y,
                                          acc[i][2] + bs0.z, acc[i][3] + bs0.w);
        *(float4*)(dst + 4) = make_float4(acc[i][4] + bs1.x, acc[i][5] + bs1.y,
                                          acc[i][6] + bs1.z, acc[i][7] + bs1.w);
    }
}

// =====================================================================
// Kernel 5: out = LayerNorm(z + residual_q) * g + b.  One block per row.
// =====================================================================
__global__ __launch_bounds__(256) void ln_kernel(
    const float* __restrict__ resid, const float* __restrict__ gam,
    const float* __restrict__ bet, float* __restrict__ out)
{
    const int row = blockIdx.x;
    const int tid = threadIdx.x;
    const float4 a = *(const float4*)(g_z   + (size_t)row * DD + tid * 4);
    const float4 r = *(const float4*)(resid + (size_t)row * DD + tid * 4);
    const float x0 = a.x + r.x, x1 = a.y + r.y, x2 = a.z + r.z, x3 = a.w + r.w;

    __shared__ float red[8];
    const float total = blockReduceSum256(x0 + x1 + x2 + x3, red);
    const float mu = total * (1.0f / (float)DD);

    const float d0 = x0 - mu, d1 = x1 - mu, d2 = x2 - mu, d3 = x3 - mu;
    const float totsq = blockReduceSum256(d0*d0 + d1*d1 + d2*d2 + d3*d3, red);
    const float w = rsqrtf(totsq * (1.0f / (float)DD) + 1e-6f);

    const float4 g4 = *(const float4*)(gam + tid * 4);
    const float4 b4 = *(const float4*)(bet + tid * 4);
    float4 o;
    o.x = d0 * w * g4.x + b4.x;
    o.y = d1 * w * g4.y + b4.y;
    o.z = d2 * w * g4.z + b4.z;
    o.w = d3 * w * g4.w + b4.w;
    *(float4*)(out + (size_t)row * DD + tid * 4) = o;
}

// =====================================================================
extern "C" void kernel_launch(void* const* d_in, const int* in_sizes, int n_in,
                              void* d_out, int out_size)
{
    (void)in_sizes; (void)n_in;
    const float* q    = (const float*)d_in[0];
    const float* k    = (const float*)d_in[1];
    const float* v    = (const float*)d_in[2];
    const int*   mask = (const int*)  d_in[3];
    const float* Wq   = (const float*)d_in[4];
    const float* bq   = (const float*)d_in[5];
    const float* Wk   = (const float*)d_in[6];
    const float* bk   = (const float*)d_in[7];
    const float* Wv   = (const float*)d_in[8];
    const float* bv   = (const float*)d_in[9];
    const float* Wo   = (const float*)d_in[10];
    const float* bo   = (const float*)d_in[11];
    const float* lng  = (const float*)d_in[12];
    const float* lnb  = (const float*)d_in[13];

    float* out = (float*)d_out;
    float* attn = ((long long)out_size >= OUT_ELEMS + ATTN_ELEMS)
                      ? (out + OUT_ELEMS) : nullptr;

    qkv_proj_kernel   <<<dim3(8, 64, 3), 256>>>(q, k, v, Wq, Wk, Wv, bq, bk, bv);
    energy_kernel     <<<dim3(16, 16, HEADS), 256>>>(mask, attn);
    stat_reduce_kernel<<<NROWS / 256, 256>>>();
    pv_kernel         <<<dim3(1, 8, HEADS), 256>>>(attn);
    outproj_kernel    <<<dim3(8, 64), 256>>>(Wo, bo);
    ln_kernel         <<<BL, 256>>>(q, lng, lnb, out);
}

// round 15
// speedup vs baseline: 1.0968x; 1.0968x over previous
#include <cuda_runtime.h>

// Problem constants
#define BB   4
#define LL   2048
#define DD   1024
#define HH   16
#define DKV  64
#define NEGV (-1e10f)

#define BL    (BB*LL)                // 8192 rows
#define HEADS (BB*HH)                // 64
static const long long OUT_ELEMS  = (long long)BB*LL*DD;          // 8,388,608
static const long long ATTN_ELEMS = (long long)BB*HH*LL*LL;       // 268,435,456

// ---------------- device scratch (no allocations allowed) ----------------
__device__ __align__(16) float g_qh [BB*HH*LL*DKV];   // [b,h,l,d] 32MB
__device__ __align__(16) float g_kh [BB*HH*LL*DKV];
__device__ __align__(16) float g_vh [BB*HH*LL*DKV];
__device__ __align__(16) float g_ctx[BB*LL*DD];       // [b,l,h*d] 32MB
__device__ __align__(16) float g_z  [BB*LL*DD];       // pre-LN    32MB
__device__ __align__(16) float g_attn_fb[268435456];  // fallback if attn not in d_out

// =====================================================================
// Kernel 1: fused QKV projections.  X[8192,1024] @ W[1024,1024] + b,
// stored directly in head layout [b,h,l,d].  z = 0/1/2 selects q/k/v.
// 128x128x8 tile, 256 threads, 8x8 per thread.
// =====================================================================
__global__ __launch_bounds__(256) void qkv_proj_kernel(
    const float* __restrict__ q, const float* __restrict__ k, const float* __restrict__ v,
    const float* __restrict__ Wq, const float* __restrict__ Wk, const float* __restrict__ Wv,
    const float* __restrict__ bq, const float* __restrict__ bk, const float* __restrict__ bv)
{
    const int zz = blockIdx.z;
    const float* __restrict__ A    = (zz == 0) ? q  : (zz == 1) ? k  : v;
    const float* __restrict__ W    = (zz == 0) ? Wq : (zz == 1) ? Wk : Wv;
    const float* __restrict__ bias = (zz == 0) ? bq : (zz == 1) ? bk : bv;
    float* __restrict__ C          = (zz == 0) ? g_qh : (zz == 1) ? g_kh : g_vh;

    __shared__ float As[8][132];   // A tile transposed [k][m], padded
    __shared__ float Bs[8][128];   // B tile natural    [k][n]

    const int tid  = threadIdx.x;
    const int tx   = tid & 15;
    const int ty   = tid >> 4;
    const int row0 = blockIdx.y * 128;
    const int col0 = blockIdx.x * 128;

    const int arow = tid >> 1;          // 0..127
    const int acol = (tid & 1) * 4;     // 0 or 4
    const int brow = tid >> 5;          // 0..7
    const int bcol = (tid & 31) * 4;    // 0..124

    float acc[8][8] = {};

    for (int kt = 0; kt < DD; kt += 8) {
        float4 a4 = *(const float4*)(A + (size_t)(row0 + arow) * DD + kt + acol);
        As[acol + 0][arow] = a4.x; As[acol + 1][arow] = a4.y;
        As[acol + 2][arow] = a4.z; As[acol + 3][arow] = a4.w;
        float4 b4 = *(const float4*)(W + (size_t)(kt + brow) * (HH * DKV) + col0 + bcol);
        *(float4*)&Bs[brow][bcol] = b4;
        __syncthreads();
        #pragma unroll
        for (int kk = 0; kk < 8; kk++) {
            float ar[8], br[8];
            #pragma unroll
            for (int i = 0; i < 8; i++) ar[i] = As[kk][ty * 8 + i];
            #pragma unroll
            for (int j = 0; j < 8; j++) br[j] = Bs[kk][tx * 8 + j];
            #pragma unroll
            for (int i = 0; i < 8; i++)
                #pragma unroll
                for (int j = 0; j < 8; j++)
                    acc[i][j] = fmaf(ar[i], br[j], acc[i][j]);
        }
        __syncthreads();
    }

    const int n0 = col0 + tx * 8;         // stays within one head (64 % 8 == 0)
    const int h  = n0 >> 6;
    const int d0 = n0 & 63;
    const float4 bs0 = *(const float4*)(bias + n0);
    const float4 bs1 = *(const float4*)(bias + n0 + 4);
    #pragma unroll
    for (int i = 0; i < 8; i++) {
        const int m  = row0 + ty * 8 + i;
        const int bb = m >> 11;           // / 2048
        const int l  = m & 2047;
        float* dst = C + (((size_t)(bb * HH + h)) * LL + l) * DKV + d0;
        float4 o0 = make_float4(acc[i][0] + bs0.x, acc[i][1] + bs0.y,
                                acc[i][2] + bs0.z, acc[i][3] + bs0.w);
        float4 o1 = make_float4(acc[i][4] + bs1.x, acc[i][5] + bs1.y,
                                acc[i][6] + bs1.z, acc[i][7] + bs1.w);
        *(float4*)dst       = o0;
        *(float4*)(dst + 4) = o1;
    }
}

// =====================================================================
// Kernel 2: energy = Q Kᵀ / 8, masked.  Per (b,h): [2048,64]x[64,2048].
// 128x128 tile, K=64.  Writes masked energy to attn buffer.
// =====================================================================
__global__ __launch_bounds__(256) void energy_kernel(
    const int* __restrict__ mask, float* __restrict__ attn_arg)
{
    float* __restrict__ attn = attn_arg ? attn_arg : g_attn_fb;
    const int z = blockIdx.z;
    const int b = z >> 4;
    const float* __restrict__ Q  = g_qh + (size_t)z * (LL * DKV);
    const float* __restrict__ Kh = g_kh + (size_t)z * (LL * DKV);
    float* __restrict__ S = attn + (size_t)z * LL * LL;

    __shared__ float As[8][132];
    __shared__ float Bs[8][132];

    const int tid  = threadIdx.x;
    const int tx   = tid & 15;
    const int ty   = tid >> 4;
    const int row0 = blockIdx.y * 128;
    const int col0 = blockIdx.x * 128;

    const int arow = tid >> 1;
    const int acol = (tid & 1) * 4;

    float acc[8][8] = {};

    #pragma unroll
    for (int kt = 0; kt < DKV; kt += 8) {
        float4 a4 = *(const float4*)(Q  + (size_t)(row0 + arow) * DKV + kt + acol);
        float4 b4 = *(const float4*)(Kh + (size_t)(col0 + arow) * DKV + kt + acol);
        As[acol + 0][arow] = a4.x; As[acol + 1][arow] = a4.y;
        As[acol + 2][arow] = a4.z; As[acol + 3][arow] = a4.w;
        Bs[acol + 0][arow] = b4.x; Bs[acol + 1][arow] = b4.y;
        Bs[acol + 2][arow] = b4.z; Bs[acol + 3][arow] = b4.w;
        __syncthreads();
        #pragma unroll
        for (int kk = 0; kk < 8; kk++) {
            float ar[8], br[8];
            #pragma unroll
            for (int i = 0; i < 8; i++) ar[i] = As[kk][ty * 8 + i];
            #pragma unroll
            for (int j = 0; j < 8; j++) br[j] = Bs[kk][tx * 8 + j];
            #pragma unroll
            for (int i = 0; i < 8; i++)
                #pragma unroll
                for (int j = 0; j < 8; j++)
                    acc[i][j] = fmaf(ar[i], br[j], acc[i][j]);
        }
        __syncthreads();
    }

    const int n0 = col0 + tx * 8;
    #pragma unroll
    for (int i = 0; i < 8; i++) {
        const int m = row0 + ty * 8 + i;
        const int* mrow = mask + ((size_t)b * LL + m) * LL + n0;
        const int4 m0 = *(const int4*)(mrow);
        const int4 m1 = *(const int4*)(mrow + 4);
        float4 o0, o1;
        o0.x = m0.x ? acc[i][0] * 0.125f : NEGV;
        o0.y = m0.y ? acc[i][1] * 0.125f : NEGV;
        o0.z = m0.z ? acc[i][2] * 0.125f : NEGV;
        o0.w = m0.w ? acc[i][3] * 0.125f : NEGV;
        o1.x = m1.x ? acc[i][4] * 0.125f : NEGV;
        o1.y = m1.y ? acc[i][5] * 0.125f : NEGV;
        o1.z = m1.z ? acc[i][6] * 0.125f : NEGV;
        o1.w = m1.w ? acc[i][7] * 0.125f : NEGV;
        float* srow = S + (size_t)m * LL + n0;
        *(float4*)srow       = o0;
        *(float4*)(srow + 4) = o1;
    }
}

// ---------------- block reductions (256 threads) ----------------
__device__ __forceinline__ float blockReduceSum256(float v, float* red) {
    #pragma unroll
    for (int o = 16; o > 0; o >>= 1) v += __shfl_xor_sync(0xffffffffu, v, o);
    const int w = threadIdx.x >> 5;
    if ((threadIdx.x & 31) == 0) red[w] = v;
    __syncthreads();
    if (threadIdx.x < 32) {
        float r = (threadIdx.x < 8) ? red[threadIdx.x] : 0.0f;
        #pragma unroll
        for (int o = 4; o > 0; o >>= 1) r += __shfl_xor_sync(0xffffffffu, r, o);
        if (threadIdx.x == 0) red[0] = r;
    }
    __syncthreads();
    const float r = red[0];
    __syncthreads();
    return r;
}

__device__ __forceinline__ float blockReduceMax256(float v, float* red) {
    #pragma unroll
    for (int o = 16; o > 0; o >>= 1) v = fmaxf(v, __shfl_xor_sync(0xffffffffu, v, o));
    const int w = threadIdx.x >> 5;
    if ((threadIdx.x & 31) == 0) red[w] = v;
    __syncthreads();
    if (threadIdx.x < 32) {
        float r = (threadIdx.x < 8) ? red[threadIdx.x] : -3.4e38f;
        #pragma unroll
        for (int o = 4; o > 0; o >>= 1) r = fmaxf(r, __shfl_xor_sync(0xffffffffu, r, o));
        if (threadIdx.x == 0) red[0] = r;
    }
    __syncthreads();
    const float r = red[0];
    __syncthreads();
    return r;
}

// =====================================================================
// Kernel 3: in-place row softmax. One block per row (2048 floats),
// 8 values/thread fully in registers.
// =====================================================================
__global__ __launch_bounds__(256) void softmax_kernel(float* __restrict__ attn_arg)
{
    float* __restrict__ attn = attn_arg ? attn_arg : g_attn_fb;
    float* p = attn + (size_t)blockIdx.x * LL;
    const int tid = threadIdx.x;

    float4 v0 = *(const float4*)(p + tid * 4);
    float4 v1 = *(const float4*)(p + 1024 + tid * 4);

    __shared__ float red[8];
    float mx = fmaxf(fmaxf(fmaxf(v0.x, v0.y), fmaxf(v0.z, v0.w)),
                     fmaxf(fmaxf(v1.x, v1.y), fmaxf(v1.z, v1.w)));
    mx = blockReduceMax256(mx, red);

    v0.x = __expf(v0.x - mx); v0.y = __expf(v0.y - mx);
    v0.z = __expf(v0.z - mx); v0.w = __expf(v0.w - mx);
    v1.x = __expf(v1.x - mx); v1.y = __expf(v1.y - mx);
    v1.z = __expf(v1.z - mx); v1.w = __expf(v1.w - mx);

    float s = (v0.x + v0.y + v0.z + v0.w) + (v1.x + v1.y + v1.z + v1.w);
    s = blockReduceSum256(s, red);
    const float inv = 1.0f / s;

    v0.x *= inv; v0.y *= inv; v0.z *= inv; v0.w *= inv;
    v1.x *= inv; v1.y *= inv; v1.z *= inv; v1.w *= inv;
    *(float4*)(p + tid * 4)        = v0;
    *(float4*)(p + 1024 + tid * 4) = v1;
}

// =====================================================================
// Kernel 4: ctx = attn @ V per (b,h): [2048,2048]x[2048,64].
// 128x64 tile, BK=16, 128 threads, 8x8 per thread (4 LDS.128 / 64 FFMA).
// Writes ctx as [b,l,h*64+d].
// =====================================================================
__global__ __launch_bounds__(128) void pv_kernel(const float* __restrict__ attn_arg)
{
    const float* __restrict__ attn = attn_arg ? attn_arg : g_attn_fb;
    const int z = blockIdx.z;
    const int b = z >> 4;
    const int h = z & 15;
    const float* __restrict__ A  = attn + (size_t)z * LL * LL;
    const float* __restrict__ Vv = g_vh + (size_t)z * (LL * DKV);

    __shared__ float As[16][132];   // [k][m] transposed, padded
    __shared__ float Bs[16][64];    // [k][n]

    const int tid  = threadIdx.x;
    const int tx   = tid & 7;     // 8 col groups of 8  -> 64 cols
    const int ty   = tid >> 3;    // 16 row groups of 8 -> 128 rows
    const int row0 = blockIdx.y * 128;

    // A loader: rows lr, lr+32, lr+64, lr+96; one float4 each
    const int lr = tid >> 2;            // 0..31
    const int lc = (tid & 3) * 4;       // 0,4,8,12
    // V loader: 16x64 tile, 2 float4 per thread
    const int brow = tid >> 3;          // 0..15
    const int bcol = (tid & 7) * 8;     // 0..56

    float acc[8][8] = {};

    for (int kt = 0; kt < LL; kt += 16) {
        #pragma unroll
        for (int qq = 0; qq < 4; qq++) {
            const int r = lr + 32 * qq;
            float4 a4 = *(const float4*)(A + (size_t)(row0 + r) * LL + kt + lc);
            As[lc + 0][r] = a4.x; As[lc + 1][r] = a4.y;
            As[lc + 2][r] = a4.z; As[lc + 3][r] = a4.w;
        }
        const float* vp = Vv + (size_t)(kt + brow) * DKV + bcol;
        *(float4*)&Bs[brow][bcol]     = *(const float4*)vp;
        *(float4*)&Bs[brow][bcol + 4] = *(const float4*)(vp + 4);
        __syncthreads();
        #pragma unroll
        for (int kk = 0; kk < 16; kk++) {
            float ar[8], br[8];
            #pragma unroll
            for (int i = 0; i < 8; i++) ar[i] = As[kk][ty * 8 + i];
            #pragma unroll
            for (int j = 0; j < 8; j++) br[j] = Bs[kk][tx * 8 + j];
            #pragma unroll
            for (int i = 0; i < 8; i++)
                #pragma unroll
                for (int j = 0; j < 8; j++)
                    acc[i][j] = fmaf(ar[i], br[j], acc[i][j]);
        }
        __syncthreads();
    }

    #pragma unroll
    for (int i = 0; i < 8; i++) {
        const int m = row0 + ty * 8 + i;
        float* dst = g_ctx + ((size_t)(b * LL + m)) * DD + h * DKV + tx * 8;
        *(float4*)dst       = make_float4(acc[i][0], acc[i][1], acc[i][2], acc[i][3]);
        *(float4*)(dst + 4) = make_float4(acc[i][4], acc[i][5], acc[i][6], acc[i][7]);
    }
}

// =====================================================================
// Kernel 5: z = ctx @ Wo + bo.  Standard 128x128x8 SGEMM, row-major out.
// =====================================================================
__global__ __launch_bounds__(256) void outproj_kernel(
    const float* __restrict__ Wo, const float* __restrict__ bo)
{
    __shared__ float As[8][132];
    __shared__ float Bs[8][128];

    const int tid  = threadIdx.x;
    const int tx   = tid & 15;
    const int ty   = tid >> 4;
    const int row0 = blockIdx.y * 128;
    const int col0 = blockIdx.x * 128;

    const int arow = tid >> 1;
    const int acol = (tid & 1) * 4;
    const int brow = tid >> 5;
    const int bcol = (tid & 31) * 4;

    float acc[8][8] = {};

    for (int kt = 0; kt < DD; kt += 8) {
        float4 a4 = *(const float4*)(g_ctx + (size_t)(row0 + arow) * DD + kt + acol);
        As[acol + 0][arow] = a4.x; As[acol + 1][arow] = a4.y;
        As[acol + 2][arow] = a4.z; As[acol + 3][arow] = a4.w;
        float4 b4 = *(const float4*)(Wo + (size_t)(kt + brow) * DD + col0 + bcol);
        *(float4*)&Bs[brow][bcol] = b4;
        __syncthreads();
        #pragma unroll
        for (int kk = 0; kk < 8; kk++) {
            float ar[8], br[8];
            #pragma unroll
            for (int i = 0; i < 8; i++) ar[i] = As[kk][ty * 8 + i];
            #pragma unroll
            for (int j = 0; j < 8; j++) br[j] = Bs[kk][tx * 8 + j];
            #pragma unroll
            for (int i = 0; i < 8; i++)
                #pragma unroll
                for (int j = 0; j < 8; j++)
                    acc[i][j] = fmaf(ar[i], br[j], acc[i][j]);
        }
        __syncthreads();
    }

    const int n0 = col0 + tx * 8;
    const float4 bs0 = *(const float4*)(bo + n0);
    const float4 bs1 = *(const float4*)(bo + n0 + 4);
    #pragma unroll
    for (int i = 0; i < 8; i++) {
        const int m = row0 + ty * 8 + i;
        float* dst = g_z + (size_t)m * DD + n0;
        *(float4*)dst       = make_float4(acc[i][0] + bs0.x, acc[i][1] + bs0.y,
                                          acc[i][2] + bs0.z, acc[i][3] + bs0.w);
        *(float4*)(dst + 4) = make_float4(acc[i][4] + bs1.x, acc[i][5] + bs1.y,
                                          acc[i][6] + bs1.z, acc[i][7] + bs1.w);
    }
}

// =====================================================================
// Kernel 6: out = LayerNorm(z + residual_q) * g + b.  One block per row.
// =====================================================================
__global__ __launch_bounds__(256) void ln_kernel(
    const float* __restrict__ resid, const float* __restrict__ gam,
    const float* __restrict__ bet, float* __restrict__ out)
{
    const int row = blockIdx.x;
    const int tid = threadIdx.x;
    const float4 a = *(const float4*)(g_z   + (size_t)row * DD + tid * 4);
    const float4 r = *(const float4*)(resid + (size_t)row * DD + tid * 4);
    const float x0 = a.x + r.x, x1 = a.y + r.y, x2 = a.z + r.z, x3 = a.w + r.w;

    __shared__ float red[8];
    const float total = blockReduceSum256(x0 + x1 + x2 + x3, red);
    const float mu = total * (1.0f / (float)DD);

    const float d0 = x0 - mu, d1 = x1 - mu, d2 = x2 - mu, d3 = x3 - mu;
    const float totsq = blockReduceSum256(d0*d0 + d1*d1 + d2*d2 + d3*d3, red);
    const float w = rsqrtf(totsq * (1.0f / (float)DD) + 1e-6f);

    const float4 g4 = *(const float4*)(gam + tid * 4);
    const float4 b4 = *(const float4*)(bet + tid * 4);
    float4 o;
    o.x = d0 * w * g4.x + b4.x;
    o.y = d1 * w * g4.y + b4.y;
    o.z = d2 * w * g4.z + b4.z;
    o.w = d3 * w * g4.w + b4.w;
    *(float4*)(out + (size_t)row * DD + tid * 4) = o;
}

// =====================================================================
extern "C" void kernel_launch(void* const* d_in, const int* in_sizes, int n_in,
                              void* d_out, int out_size)
{
    (void)in_sizes; (void)n_in;
    const float* q    = (const float*)d_in[0];
    const float* k    = (const float*)d_in[1];
    const float* v    = (const float*)d_in[2];
    const int*   mask = (const int*)  d_in[3];
    const float* Wq   = (const float*)d_in[4];
    const float* bq   = (const float*)d_in[5];
    const float* Wk   = (const float*)d_in[6];
    const float* bk   = (const float*)d_in[7];
    const float* Wv   = (const float*)d_in[8];
    const float* bv   = (const float*)d_in[9];
    const float* Wo   = (const float*)d_in[10];
    const float* bo   = (const float*)d_in[11];
    const float* lng  = (const float*)d_in[12];
    const float* lnb  = (const float*)d_in[13];

    float* out = (float*)d_out;
    // attn goes in d_out after `out` if the output buffer holds both tensors;
    // otherwise kernels fall back to the __device__ scratch array.
    float* attn = ((long long)out_size >= OUT_ELEMS + ATTN_ELEMS)
                      ? (out + OUT_ELEMS) : nullptr;

    qkv_proj_kernel<<<dim3(8, 64, 3), 256>>>(q, k, v, Wq, Wk, Wv, bq, bk, bv);
    energy_kernel  <<<dim3(16, 16, HEADS), 256>>>(mask, attn);
    softmax_kernel <<<BB * HH * LL, 256>>>(attn);
    pv_kernel      <<<dim3(1, 16, HEADS), 128>>>(attn);
    outproj_kernel <<<dim3(8, 64), 256>>>(Wo, bo);
    ln_kernel      <<<BL, 256>>>(q, lng, lnb, out);
}

// round 17
// speedup vs baseline: 1.3774x; 1.2559x over previous
#include <cuda_runtime.h>

// Problem constants
#define BB   4
#define LL   2048
#define DD   1024
#define HH   16
#define DKV  64
#define NEGV (-1e10f)

#define BL    (BB*LL)                // 8192 rows
#define HEADS (BB*HH)                // 64
static const long long OUT_ELEMS  = (long long)BB*LL*DD;          // 8,388,608
static const long long ATTN_ELEMS = (long long)BB*HH*LL*LL;       // 268,435,456

// ---------------- device scratch (no allocations allowed) ----------------
__device__ __align__(16) float g_qh [BB*HH*LL*DKV];   // [b,h,l,d] 32MB
__device__ __align__(16) float g_kh [BB*HH*LL*DKV];
__device__ __align__(16) float g_vh [BB*HH*LL*DKV];
__device__ __align__(16) float g_ctx[BB*LL*DD];       // [b,l,h*d] 32MB
__device__ __align__(16) float g_z  [BB*LL*DD];       // pre-LN    32MB
__device__ __align__(16) float g_attn_fb[268435456];  // fallback if attn not in d_out

// ---------------- tensor-core helpers (sm_80-era mma.sync, legal on sm_103) --
__device__ __forceinline__ unsigned to_tf32(float x) {
    unsigned y;
    asm("cvt.rna.tf32.f32 %0, %1;" : "=r"(y) : "f"(x));
    return y;
}
__device__ __forceinline__ void mma_tf32(float* c, const unsigned* a, const unsigned* b) {
    asm volatile(
        "mma.sync.aligned.m16n8k8.row.col.f32.tf32.tf32.f32 "
        "{%0,%1,%2,%3}, {%4,%5,%6,%7}, {%8,%9}, {%0,%1,%2,%3};"
        : "+f"(c[0]), "+f"(c[1]), "+f"(c[2]), "+f"(c[3])
        : "r"(a[0]), "r"(a[1]), "r"(a[2]), "r"(a[3]), "r"(b[0]), "r"(b[1]));
}

// =====================================================================
// Kernel 1: fused QKV projections via tf32 mma.sync.
// X[8192,1024] @ W[1024,1024] + b -> head layout [b,h,l,d].
// CTA 128x128, BK=16 double-buffered, 8 warps (2x4), warp tile 64x32.
// =====================================================================
__global__ __launch_bounds__(256) void qkv_tc_kernel(
    const float* __restrict__ q, const float* __restrict__ k, const float* __restrict__ v,
    const float* __restrict__ Wq, const float* __restrict__ Wk, const float* __restrict__ Wv,
    const float* __restrict__ bq, const float* __restrict__ bk, const float* __restrict__ bv)
{
    const int zz = blockIdx.z;
    const float* __restrict__ X    = (zz == 0) ? q  : (zz == 1) ? k  : v;
    const float* __restrict__ W    = (zz == 0) ? Wq : (zz == 1) ? Wk : Wv;
    const float* __restrict__ bias = (zz == 0) ? bq : (zz == 1) ? bk : bv;
    float* __restrict__ C          = (zz == 0) ? g_qh : (zz == 1) ? g_kh : g_vh;

    __shared__ float As[2][16][132];   // [k][m] (tf32 bits)
    __shared__ float Bs[2][16][132];   // [k][n] (tf32 bits)

    const int tid  = threadIdx.x;
    const int lane = tid & 31;
    const int warp = tid >> 5;
    const int g    = lane >> 2;        // 0..7
    const int tig  = lane & 3;         // 0..3
    const int wm   = warp >> 2;        // 0..1
    const int wn   = warp & 3;         // 0..3
    const int row0 = blockIdx.y * 128;
    const int col0 = blockIdx.x * 128;
    const int m0   = wm * 64;
    const int n0   = wn * 32;

    const int arow = tid >> 1;         // 0..127
    const int ac   = (tid & 1) * 8;    // 0 or 8
    const int brow = tid >> 4;         // 0..15
    const int bc   = (tid & 15) * 8;   // 0..120

    float4 a0r, a1r, b0r, b1r;
    {   // prologue: chunk 0
        const float* Xp = X + (size_t)(row0 + arow) * DD + ac;
        a0r = *(const float4*)Xp; a1r = *(const float4*)(Xp + 4);
        const float* Wp = W + (size_t)brow * DD + col0 + bc;
        b0r = *(const float4*)Wp; b1r = *(const float4*)(Wp + 4);
    }

    float acc[4][4][4] = {};

    for (int kt = 0; kt < 64; kt++) {
        const int buf = kt & 1;
        // store prefetched chunk to smem (tf32-converted)
        As[buf][ac + 0][arow] = __uint_as_float(to_tf32(a0r.x));
        As[buf][ac + 1][arow] = __uint_as_float(to_tf32(a0r.y));
        As[buf][ac + 2][arow] = __uint_as_float(to_tf32(a0r.z));
        As[buf][ac + 3][arow] = __uint_as_float(to_tf32(a0r.w));
        As[buf][ac + 4][arow] = __uint_as_float(to_tf32(a1r.x));
        As[buf][ac + 5][arow] = __uint_as_float(to_tf32(a1r.y));
        As[buf][ac + 6][arow] = __uint_as_float(to_tf32(a1r.z));
        As[buf][ac + 7][arow] = __uint_as_float(to_tf32(a1r.w));
        {
            float4 c0, c1;
            c0.x = __uint_as_float(to_tf32(b0r.x)); c0.y = __uint_as_float(to_tf32(b0r.y));
            c0.z = __uint_as_float(to_tf32(b0r.z)); c0.w = __uint_as_float(to_tf32(b0r.w));
            c1.x = __uint_as_float(to_tf32(b1r.x)); c1.y = __uint_as_float(to_tf32(b1r.y));
            c1.z = __uint_as_float(to_tf32(b1r.z)); c1.w = __uint_as_float(to_tf32(b1r.w));
            *(float4*)&Bs[buf][brow][bc]     = c0;
            *(float4*)&Bs[buf][brow][bc + 4] = c1;
        }
        __syncthreads();

        if (kt < 63) {   // prefetch next chunk, overlapped with MMA below
            const float* Xp = X + (size_t)(row0 + arow) * DD + (kt + 1) * 16 + ac;
            a0r = *(const float4*)Xp; a1r = *(const float4*)(Xp + 4);
            const float* Wp = W + (size_t)((kt + 1) * 16 + brow) * DD + col0 + bc;
            b0r = *(const float4*)Wp; b1r = *(const float4*)(Wp + 4);
        }

        #pragma unroll
        for (int s = 0; s < 2; s++) {
            const int k0 = s * 8;
            unsigned af[4][4], bf[4][2];
            #pragma unroll
            for (int i = 0; i < 4; i++) {
                const int m = m0 + 16 * i + g;
                af[i][0] = __float_as_uint(As[buf][k0 + tig    ][m]);
                af[i][1] = __float_as_uint(As[buf][k0 + tig    ][m + 8]);
                af[i][2] = __float_as_uint(As[buf][k0 + tig + 4][m]);
                af[i][3] = __float_as_uint(As[buf][k0 + tig + 4][m + 8]);
            }
            #pragma unroll
            for (int j = 0; j < 4; j++) {
                const int n = n0 + 8 * j + g;
                bf[j][0] = __float_as_uint(Bs[buf][k0 + tig    ][n]);
                bf[j][1] = __float_as_uint(Bs[buf][k0 + tig + 4][n]);
            }
            #pragma unroll
            for (int i = 0; i < 4; i++)
                #pragma unroll
                for (int j = 0; j < 4; j++)
                    mma_tf32(acc[i][j], af[i], bf[j]);
        }
        __syncthreads();
    }

    // epilogue: bias + head-layout store [b,h,l,d]
    #pragma unroll
    for (int i = 0; i < 4; i++) {
        const int mA = row0 + m0 + 16 * i + g;
        const int mB = mA + 8;
        const int bbA = mA >> 11, lA = mA & 2047;
        const int bbB = mB >> 11, lB = mB & 2047;
        #pragma unroll
        for (int j = 0; j < 4; j++) {
            const int n = col0 + n0 + 8 * j + 2 * tig;
            const int h = n >> 6, d = n & 63;
            const float2 bi = *(const float2*)(bias + n);
            *(float2*)(C + (((size_t)(bbA * HH + h)) * LL + lA) * DKV + d) =
                make_float2(acc[i][j][0] + bi.x, acc[i][j][1] + bi.y);
            *(float2*)(C + (((size_t)(bbB * HH + h)) * LL + lB) * DKV + d) =
                make_float2(acc[i][j][2] + bi.x, acc[i][j][3] + bi.y);
        }
    }
}

// =====================================================================
// Kernel 5 (tensor-core): z = ctx @ Wo + bo.  Same tile machinery,
// row-major output.
// =====================================================================
__global__ __launch_bounds__(256) void outproj_tc_kernel(
    const float* __restrict__ Wo, const float* __restrict__ bo)
{
    __shared__ float As[2][16][132];
    __shared__ float Bs[2][16][132];

    const int tid  = threadIdx.x;
    const int lane = tid & 31;
    const int warp = tid >> 5;
    const int g    = lane >> 2;
    const int tig  = lane & 3;
    const int wm   = warp >> 2;
    const int wn   = warp & 3;
    const int row0 = blockIdx.y * 128;
    const int col0 = blockIdx.x * 128;
    const int m0   = wm * 64;
    const int n0   = wn * 32;

    const int arow = tid >> 1;
    const int ac   = (tid & 1) * 8;
    const int brow = tid >> 4;
    const int bc   = (tid & 15) * 8;

    float4 a0r, a1r, b0r, b1r;
    {
        const float* Xp = g_ctx + (size_t)(row0 + arow) * DD + ac;
        a0r = *(const float4*)Xp; a1r = *(const float4*)(Xp + 4);
        const float* Wp = Wo + (size_t)brow * DD + col0 + bc;
        b0r = *(const float4*)Wp; b1r = *(const float4*)(Wp + 4);
    }

    float acc[4][4][4] = {};

    for (int kt = 0; kt < 64; kt++) {
        const int buf = kt & 1;
        As[buf][ac + 0][arow] = __uint_as_float(to_tf32(a0r.x));
        As[buf][ac + 1][arow] = __uint_as_float(to_tf32(a0r.y));
        As[buf][ac + 2][arow] = __uint_as_float(to_tf32(a0r.z));
        As[buf][ac + 3][arow] = __uint_as_float(to_tf32(a0r.w));
        As[buf][ac + 4][arow] = __uint_as_float(to_tf32(a1r.x));
        As[buf][ac + 5][arow] = __uint_as_float(to_tf32(a1r.y));
        As[buf][ac + 6][arow] = __uint_as_float(to_tf32(a1r.z));
        As[buf][ac + 7][arow] = __uint_as_float(to_tf32(a1r.w));
        {
            float4 c0, c1;
            c0.x = __uint_as_float(to_tf32(b0r.x)); c0.y = __uint_as_float(to_tf32(b0r.y));
            c0.z = __uint_as_float(to_tf32(b0r.z)); c0.w = __uint_as_float(to_tf32(b0r.w));
            c1.x = __uint_as_float(to_tf32(b1r.x)); c1.y = __uint_as_float(to_tf32(b1r.y));
            c1.z = __uint_as_float(to_tf32(b1r.z)); c1.w = __uint_as_float(to_tf32(b1r.w));
            *(float4*)&Bs[buf][brow][bc]     = c0;
            *(float4*)&Bs[buf][brow][bc + 4] = c1;
        }
        __syncthreads();

        if (kt < 63) {
            const float* Xp = g_ctx + (size_t)(row0 + arow) * DD + (kt + 1) * 16 + ac;
            a0r = *(const float4*)Xp; a1r = *(const float4*)(Xp + 4);
            const float* Wp = Wo + (size_t)((kt + 1) * 16 + brow) * DD + col0 + bc;
            b0r = *(const float4*)Wp; b1r = *(const float4*)(Wp + 4);
        }

        #pragma unroll
        for (int s = 0; s < 2; s++) {
            const int k0 = s * 8;
            unsigned af[4][4], bf[4][2];
            #pragma unroll
            for (int i = 0; i < 4; i++) {
                const int m = m0 + 16 * i + g;
                af[i][0] = __float_as_uint(As[buf][k0 + tig    ][m]);
                af[i][1] = __float_as_uint(As[buf][k0 + tig    ][m + 8]);
                af[i][2] = __float_as_uint(As[buf][k0 + tig + 4][m]);
                af[i][3] = __float_as_uint(As[buf][k0 + tig + 4][m + 8]);
            }
            #pragma unroll
            for (int j = 0; j < 4; j++) {
                const int n = n0 + 8 * j + g;
                bf[j][0] = __float_as_uint(Bs[buf][k0 + tig    ][n]);
                bf[j][1] = __float_as_uint(Bs[buf][k0 + tig + 4][n]);
            }
            #pragma unroll
            for (int i = 0; i < 4; i++)
                #pragma unroll
                for (int j = 0; j < 4; j++)
                    mma_tf32(acc[i][j], af[i], bf[j]);
        }
        __syncthreads();
    }

    #pragma unroll
    for (int i = 0; i < 4; i++) {
        const int mA = row0 + m0 + 16 * i + g;
        const int mB = mA + 8;
        #pragma unroll
        for (int j = 0; j < 4; j++) {
            const int n = col0 + n0 + 8 * j + 2 * tig;
            const float2 bi = *(const float2*)(bo + n);
            *(float2*)(g_z + (size_t)mA * DD + n) =
                make_float2(acc[i][j][0] + bi.x, acc[i][j][1] + bi.y);
            *(float2*)(g_z + (size_t)mB * DD + n) =
                make_float2(acc[i][j][2] + bi.x, acc[i][j][3] + bi.y);
        }
    }
}

// =====================================================================
// Kernel 2: energy = Q Kᵀ / 8, masked.  Per (b,h): [2048,64]x[64,2048].
// 128x128 tile, K=64.  Writes masked energy to attn buffer.
// =====================================================================
__global__ __launch_bounds__(256) void energy_kernel(
    const int* __restrict__ mask, float* __restrict__ attn_arg)
{
    float* __restrict__ attn = attn_arg ? attn_arg : g_attn_fb;
    const int z = blockIdx.z;
    const int b = z >> 4;
    const float* __restrict__ Q  = g_qh + (size_t)z * (LL * DKV);
    const float* __restrict__ Kh = g_kh + (size_t)z * (LL * DKV);
    float* __restrict__ S = attn + (size_t)z * LL * LL;

    __shared__ float As[8][132];
    __shared__ float Bs[8][132];

    const int tid  = threadIdx.x;
    const int tx   = tid & 15;
    const int ty   = tid >> 4;
    const int row0 = blockIdx.y * 128;
    const int col0 = blockIdx.x * 128;

    const int arow = tid >> 1;
    const int acol = (tid & 1) * 4;

    float acc[8][8] = {};

    #pragma unroll
    for (int kt = 0; kt < DKV; kt += 8) {
        float4 a4 = *(const float4*)(Q  + (size_t)(row0 + arow) * DKV + kt + acol);
        float4 b4 = *(const float4*)(Kh + (size_t)(col0 + arow) * DKV + kt + acol);
        As[acol + 0][arow] = a4.x; As[acol + 1][arow] = a4.y;
        As[acol + 2][arow] = a4.z; As[acol + 3][arow] = a4.w;
        Bs[acol + 0][arow] = b4.x; Bs[acol + 1][arow] = b4.y;
        Bs[acol + 2][arow] = b4.z; Bs[acol + 3][arow] = b4.w;
        __syncthreads();
        #pragma unroll
        for (int kk = 0; kk < 8; kk++) {
            float ar[8], br[8];
            #pragma unroll
            for (int i = 0; i < 8; i++) ar[i] = As[kk][ty * 8 + i];
            #pragma unroll
            for (int j = 0; j < 8; j++) br[j] = Bs[kk][tx * 8 + j];
            #pragma unroll
            for (int i = 0; i < 8; i++)
                #pragma unroll
                for (int j = 0; j < 8; j++)
                    acc[i][j] = fmaf(ar[i], br[j], acc[i][j]);
        }
        __syncthreads();
    }

    const int n0 = col0 + tx * 8;
    #pragma unroll
    for (int i = 0; i < 8; i++) {
        const int m = row0 + ty * 8 + i;
        const int* mrow = mask + ((size_t)b * LL + m) * LL + n0;
        const int4 m0 = *(const int4*)(mrow);
        const int4 m1 = *(const int4*)(mrow + 4);
        float4 o0, o1;
        o0.x = m0.x ? acc[i][0] * 0.125f : NEGV;
        o0.y = m0.y ? acc[i][1] * 0.125f : NEGV;
        o0.z = m0.z ? acc[i][2] * 0.125f : NEGV;
        o0.w = m0.w ? acc[i][3] * 0.125f : NEGV;
        o1.x = m1.x ? acc[i][4] * 0.125f : NEGV;
        o1.y = m1.y ? acc[i][5] * 0.125f : NEGV;
        o1.z = m1.z ? acc[i][6] * 0.125f : NEGV;
        o1.w = m1.w ? acc[i][7] * 0.125f : NEGV;
        float* srow = S + (size_t)m * LL + n0;
        *(float4*)srow       = o0;
        *(float4*)(srow + 4) = o1;
    }
}

// ---------------- block reductions (256 threads) ----------------
__device__ __forceinline__ float blockReduceSum256(float v, float* red) {
    #pragma unroll
    for (int o = 16; o > 0; o >>= 1) v += __shfl_xor_sync(0xffffffffu, v, o);
    const int w = threadIdx.x >> 5;
    if ((threadIdx.x & 31) == 0) red[w] = v;
    __syncthreads();
    if (threadIdx.x < 32) {
        float r = (threadIdx.x < 8) ? red[threadIdx.x] : 0.0f;
        #pragma unroll
        for (int o = 4; o > 0; o >>= 1) r += __shfl_xor_sync(0xffffffffu, r, o);
        if (threadIdx.x == 0) red[0] = r;
    }
    __syncthreads();
    const float r = red[0];
    __syncthreads();
    return r;
}

__device__ __forceinline__ float blockReduceMax256(float v, float* red) {
    #pragma unroll
    for (int o = 16; o > 0; o >>= 1) v = fmaxf(v, __shfl_xor_sync(0xffffffffu, v, o));
    const int w = threadIdx.x >> 5;
    if ((threadIdx.x & 31) == 0) red[w] = v;
    __syncthreads();
    if (threadIdx.x < 32) {
        float r = (threadIdx.x < 8) ? red[threadIdx.x] : -3.4e38f;
        #pragma unroll
        for (int o = 4; o > 0; o >>= 1) r = fmaxf(r, __shfl_xor_sync(0xffffffffu, r, o));
        if (threadIdx.x == 0) red[0] = r;
    }
    __syncthreads();
    const float r = red[0];
    __syncthreads();
    return r;
}

// =====================================================================
// Kernel 3: in-place row softmax. One block per row (2048 floats).
// =====================================================================
__global__ __launch_bounds__(256) void softmax_kernel(float* __restrict__ attn_arg)
{
    float* __restrict__ attn = attn_arg ? attn_arg : g_attn_fb;
    float* p = attn + (size_t)blockIdx.x * LL;
    const int tid = threadIdx.x;

    float4 v0 = *(const float4*)(p + tid * 4);
    float4 v1 = *(const float4*)(p + 1024 + tid * 4);

    __shared__ float red[8];
    float mx = fmaxf(fmaxf(fmaxf(v0.x, v0.y), fmaxf(v0.z, v0.w)),
                     fmaxf(fmaxf(v1.x, v1.y), fmaxf(v1.z, v1.w)));
    mx = blockReduceMax256(mx, red);

    v0.x = __expf(v0.x - mx); v0.y = __expf(v0.y - mx);
    v0.z = __expf(v0.z - mx); v0.w = __expf(v0.w - mx);
    v1.x = __expf(v1.x - mx); v1.y = __expf(v1.y - mx);
    v1.z = __expf(v1.z - mx); v1.w = __expf(v1.w - mx);

    float s = (v0.x + v0.y + v0.z + v0.w) + (v1.x + v1.y + v1.z + v1.w);
    s = blockReduceSum256(s, red);
    const float inv = 1.0f / s;

    v0.x *= inv; v0.y *= inv; v0.z *= inv; v0.w *= inv;
    v1.x *= inv; v1.y *= inv; v1.z *= inv; v1.w *= inv;
    *(float4*)(p + tid * 4)        = v0;
    *(float4*)(p + 1024 + tid * 4) = v1;
}

// =====================================================================
// Kernel 4: ctx = attn @ V per (b,h): [2048,2048]x[2048,64].
// 128x64 tile, BK=16, 256 threads, 8x4 per thread. Writes [b,l,h*64+d].
// =====================================================================
__global__ __launch_bounds__(256) void pv_kernel(const float* __restrict__ attn_arg)
{
    const float* __restrict__ attn = attn_arg ? attn_arg : g_attn_fb;
    const int z = blockIdx.z;
    const int b = z >> 4;
    const int h = z & 15;
    const float* __restrict__ A  = attn + (size_t)z * LL * LL;
    const float* __restrict__ Vv = g_vh + (size_t)z * (LL * DKV);

    __shared__ float As[16][132];
    __shared__ float Bs[16][64];

    const int tid  = threadIdx.x;
    const int tx   = tid & 15;   // 4 cols each
    const int ty   = tid >> 4;   // 8 rows each
    const int row0 = blockIdx.y * 128;

    const int arow0 = tid >> 2;        // 0..63
    const int acol  = (tid & 3) * 4;   // 0,4,8,12
    const int brow  = tid >> 4;        // 0..15
    const int bcol  = (tid & 15) * 4;  // 0..60

    float acc[8][4] = {};

    for (int kt = 0; kt < LL; kt += 16) {
        #pragma unroll
        for (int it = 0; it < 2; it++) {
            const int arow = arow0 + it * 64;
            float4 a4 = *(const float4*)(A + (size_t)(row0 + arow) * LL + kt + acol);
            As[acol + 0][arow] = a4.x; As[acol + 1][arow] = a4.y;
            As[acol + 2][arow] = a4.z; As[acol + 3][arow] = a4.w;
        }
        float4 b4 = *(const float4*)(Vv + (size_t)(kt + brow) * DKV + bcol);
        *(float4*)&Bs[brow][bcol] = b4;
        __syncthreads();
        #pragma unroll
        for (int kk = 0; kk < 16; kk++) {
            float ar[8], br[4];
            #pragma unroll
            for (int i = 0; i < 8; i++) ar[i] = As[kk][ty * 8 + i];
            #pragma unroll
            for (int j = 0; j < 4; j++) br[j] = Bs[kk][tx * 4 + j];
            #pragma unroll
            for (int i = 0; i < 8; i++)
                #pragma unroll
                for (int j = 0; j < 4; j++)
                    acc[i][j] = fmaf(ar[i], br[j], acc[i][j]);
        }
        __syncthreads();
    }

    #pragma unroll
    for (int i = 0; i < 8; i++) {
        const int m = row0 + ty * 8 + i;
        float4 o = make_float4(acc[i][0], acc[i][1], acc[i][2], acc[i][3]);
        *(float4*)(g_ctx + ((size_t)(b * LL + m)) * DD + h * DKV + tx * 4) = o;
    }
}

// =====================================================================
// Kernel 6: out = LayerNorm(z + residual_q) * g + b.  One block per row.
// =====================================================================
__global__ __launch_bounds__(256) void ln_kernel(
    const float* __restrict__ resid, const float* __restrict__ gam,
    const float* __restrict__ bet, float* __restrict__ out)
{
    const int row = blockIdx.x;
    const int tid = threadIdx.x;
    const float4 a = *(const float4*)(g_z   + (size_t)row * DD + tid * 4);
    const float4 r = *(const float4*)(resid + (size_t)row * DD + tid * 4);
    const float x0 = a.x + r.x, x1 = a.y + r.y, x2 = a.z + r.z, x3 = a.w + r.w;

    __shared__ float red[8];
    const float total = blockReduceSum256(x0 + x1 + x2 + x3, red);
    const float mu = total * (1.0f / (float)DD);

    const float d0 = x0 - mu, d1 = x1 - mu, d2 = x2 - mu, d3 = x3 - mu;
    const float totsq = blockReduceSum256(d0*d0 + d1*d1 + d2*d2 + d3*d3, red);
    const float w = rsqrtf(totsq * (1.0f / (float)DD) + 1e-6f);

    const float4 g4 = *(const float4*)(gam + tid * 4);
    const float4 b4 = *(const float4*)(bet + tid * 4);
    float4 o;
    o.x = d0 * w * g4.x + b4.x;
    o.y = d1 * w * g4.y + b4.y;
    o.z = d2 * w * g4.z + b4.z;
    o.w = d3 * w * g4.w + b4.w;
    *(float4*)(out + (size_t)row * DD + tid * 4) = o;
}

// =====================================================================
extern "C" void kernel_launch(void* const* d_in, const int* in_sizes, int n_in,
                              void* d_out, int out_size)
{
    (void)in_sizes; (void)n_in;
    const float* q    = (const float*)d_in[0];
    const float* k    = (const float*)d_in[1];
    const float* v    = (const float*)d_in[2];
    const int*   mask = (const int*)  d_in[3];
    const float* Wq   = (const float*)d_in[4];
    const float* bq   = (const float*)d_in[5];
    const float* Wk   = (const float*)d_in[6];
    const float* bk   = (const float*)d_in[7];
    const float* Wv   = (const float*)d_in[8];
    const float* bv   = (const float*)d_in[9];
    const float* Wo   = (const float*)d_in[10];
    const float* bo   = (const float*)d_in[11];
    const float* lng  = (const float*)d_in[12];
    const float* lnb  = (const float*)d_in[13];

    float* out = (float*)d_out;
    // attn goes in d_out after `out` if the output buffer holds both tensors;
    // otherwise kernels fall back to the __device__ scratch array.
    float* attn = ((long long)out_size >= OUT_ELEMS + ATTN_ELEMS)
                      ? (out + OUT_ELEMS) : nullptr;

    qkv_tc_kernel    <<<dim3(8, 64, 3), 256>>>(q, k, v, Wq, Wk, Wv, bq, bk, bv);
    energy_kernel    <<<dim3(16, 16, HEADS), 256>>>(mask, attn);
    softmax_kernel   <<<BB * HH * LL, 256>>>(attn);
    pv_kernel        <<<dim3(1, 16, HEADS), 256>>>(attn);
    outproj_tc_kernel<<<dim3(8, 64), 256>>>(Wo, bo);
    ln_kernel        <<<BL, 256>>>(q, lng, lnb, out);
}